// round 1
// baseline (speedup 1.0000x reference)
#include <cuda_runtime.h>
#include <math.h>

#define SS 256
#define BB 32
#define EE 768
#define HH 512
#define CC 30
#define MTOT (SS*BB)      // 8192
#define G4 2048
#define K0P 776           // 770 padded to multiple of 8
#define K1 1024

// ---------------- scratch (device globals; no allocation allowed) ----------
__device__ float d_x0[(size_t)MTOT * K0P];          // layer0 input, padded, [s*32+b][776]
__device__ float d_meanword[MTOT];                  // [b][s]
__device__ float d_meanpred[BB];
__device__ float d_wpad[2][(size_t)G4 * K0P];       // padded Wih_l0 (f,b)
__device__ float d_G[2][(size_t)MTOT * G4];         // gate preactivations (xW+bias), per dir
__device__ float d_hT[2][(size_t)(SS+1) * HH * BB]; // h states, [dir][slot][k][b]
__device__ float d_cst[2][HH * BB];                 // c state [dir][k][b]
__device__ float d_x1[(size_t)MTOT * K1];           // layer1 input [s*32+b][1024]
__device__ float d_x2[(size_t)MTOT * K1];           // layer2 output (final proj input)

__device__ __forceinline__ float sigmf(float x) { return 0.5f + 0.5f * tanhf(0.5f * x); }

// ---------------- feature prep ---------------------------------------------
__global__ __launch_bounds__(256) void prep_mean(const float* __restrict__ hs) {
    int b = blockIdx.x >> 8;
    int s = blockIdx.x & 255;
    int tid = threadIdx.x;
    const size_t L = (size_t)BB * SS * EE;
    const float* p = hs + ((size_t)b * SS + s) * EE;
    float* xrow = d_x0 + ((size_t)s * BB + b) * K0P;
    float lsum = 0.f;
    for (int e = tid; e < EE; e += 256) {
        float v = 0.25f * (p[e] + p[e + L] + p[e + 2 * L] + p[e + 3 * L]);
        xrow[e] = v;
        lsum += v;
    }
    __shared__ float red[256];
    red[tid] = lsum;
    __syncthreads();
    for (int o = 128; o > 0; o >>= 1) {
        if (tid < o) red[tid] += red[tid + o];
        __syncthreads();
    }
    if (tid == 0) d_meanword[b * SS + s] = red[0] * (1.0f / 768.0f);
    if (tid < 6) xrow[770 + tid] = 0.f;  // zero pad cols
}

__global__ void predk(const int* __restrict__ pred) {
    int b = threadIdx.x;  // 32 threads
    const int* p = pred + b * SS;
    int best = p[0], idx = 0;
    for (int s = 1; s < SS; s++) {
        if (p[s] > best) { best = p[s]; idx = s; }
    }
    d_meanpred[b] = d_meanword[b * SS + idx];
}

__global__ __launch_bounds__(256) void finishx(const int* __restrict__ roles) {
    int i = blockIdx.x * 256 + threadIdx.x;  // 8192 = b*256+s
    int b = i >> 8, s = i & 255;
    float* xrow = d_x0 + ((size_t)s * BB + b) * K0P;
    xrow[EE] = d_meanword[i] - d_meanpred[b];
    int r = roles[i];
    xrow[EE + 1] = (r != 0 && r != -100) ? 1.f : 0.f;
}

__global__ __launch_bounds__(256) void wpadk(const float* __restrict__ w0,
                                             const float* __restrict__ w1) {
    size_t i = (size_t)blockIdx.x * 256 + threadIdx.x;
    const size_t per = (size_t)G4 * K0P;
    if (i >= 2 * per) return;
    int dir = (int)(i / per);
    size_t r = i % per;
    int row = (int)(r / K0P), col = (int)(r % K0P);
    const float* w = dir ? w1 : w0;
    d_wpad[dir][r] = (col < 770) ? w[(size_t)row * 770 + col] : 0.f;
}

// ---------------- input-projection GEMM: C[M,2048] = A[M,K]*W[2048,K]^T + b1+b2
__global__ __launch_bounds__(256) void sgemm_bias(const float* __restrict__ Wext,
                                                  const float* __restrict__ b1,
                                                  const float* __restrict__ b2,
                                                  int dir, int layer) {
    const int K = layer ? K1 : K0P;
    const float* A = layer ? d_x1 : d_x0;
    const float* W = layer ? Wext : d_wpad[dir];
    float* C = d_G[dir];

    __shared__ float Asm[8][128];
    __shared__ float Bsm[8][128];
    int tid = threadIdx.x;
    int m0 = blockIdx.y * 128, n0 = blockIdx.x * 128;
    int lr = tid >> 1, lc = (tid & 1) * 4;
    int tx = tid & 15, ty = tid >> 4;

    float acc[8][8];
#pragma unroll
    for (int i = 0; i < 8; i++)
#pragma unroll
        for (int j = 0; j < 8; j++) acc[i][j] = 0.f;

    const float* Ap = A + (size_t)(m0 + lr) * K + lc;
    const float* Wp = W + (size_t)(n0 + lr) * K + lc;

    for (int k0 = 0; k0 < K; k0 += 8) {
        float4 av = *(const float4*)(Ap + k0);
        float4 wv = *(const float4*)(Wp + k0);
        __syncthreads();
        Asm[lc + 0][lr] = av.x; Asm[lc + 1][lr] = av.y;
        Asm[lc + 2][lr] = av.z; Asm[lc + 3][lr] = av.w;
        Bsm[lc + 0][lr] = wv.x; Bsm[lc + 1][lr] = wv.y;
        Bsm[lc + 2][lr] = wv.z; Bsm[lc + 3][lr] = wv.w;
        __syncthreads();
#pragma unroll
        for (int kk = 0; kk < 8; kk++) {
            float4 a0 = *(const float4*)&Asm[kk][ty * 8];
            float4 a1 = *(const float4*)&Asm[kk][ty * 8 + 4];
            float4 c0 = *(const float4*)&Bsm[kk][tx * 8];
            float4 c1 = *(const float4*)&Bsm[kk][tx * 8 + 4];
            float aa[8] = {a0.x, a0.y, a0.z, a0.w, a1.x, a1.y, a1.z, a1.w};
            float bb[8] = {c0.x, c0.y, c0.z, c0.w, c1.x, c1.y, c1.z, c1.w};
#pragma unroll
            for (int i = 0; i < 8; i++)
#pragma unroll
                for (int j = 0; j < 8; j++) acc[i][j] = fmaf(aa[i], bb[j], acc[i][j]);
        }
    }
    float bs[8];
#pragma unroll
    for (int j = 0; j < 8; j++) bs[j] = b1[n0 + tx * 8 + j] + b2[n0 + tx * 8 + j];
#pragma unroll
    for (int i = 0; i < 8; i++)
#pragma unroll
        for (int j = 0; j < 8; j++)
            C[(size_t)(m0 + ty * 8 + i) * G4 + n0 + tx * 8 + j] = acc[i][j] + bs[j];
}

// ---------------- one LSTM timestep, both directions ------------------------
// grid 128: blocks 0..63 fwd, 64..127 bwd. Each block: 8 h-indices (j), all 32 batches.
__global__ __launch_bounds__(256) void lstm_step(const float* __restrict__ WhhF,
                                                 const float* __restrict__ WhhB,
                                                 int t, int layer) {
    int dir = blockIdx.x >> 6;
    int jb = blockIdx.x & 63;
    int j0 = jb * 8;
    const float* Whh = dir ? WhhB : WhhF;
    int s = dir ? (SS - 1 - t) : t;
    int prevslot = dir ? (s + 1) : t;
    int storeslot = dir ? s : (t + 1);

    const float* hprev = d_hT[dir] + (size_t)prevslot * (HH * BB);
    float* hout = d_hT[dir] + (size_t)storeslot * (HH * BB);
    float* cbuf = d_cst[dir];
    const float* Gp = d_G[dir] + (size_t)s * BB * G4;
    float* xcat = (layer ? d_x2 : d_x1) + (size_t)s * BB * K1 + dir * HH;

    int tid = threadIdx.x;
    int tx = tid & 7, ty = tid >> 3;  // tx=j offset, ty=batch
    float acc0 = 0.f, acc1 = 0.f, acc2 = 0.f, acc3 = 0.f;

    __shared__ float As[32][32];   // h chunk [k][b]
    __shared__ float Ws[32][36];   // weights [k][j*4+gate], padded

    if (t > 0) {
        int wr = tid >> 3;         // 0..31 -> (j = wr>>2, gate = wr&3)
        int wl = tid & 7;
        int wj = wr >> 2, wg = wr & 3;
        const float* wrow = Whh + (size_t)(wg * HH + j0 + wj) * HH + wl * 4;
        const float* hsrc = hprev + tid * 4;
        for (int k0 = 0; k0 < HH; k0 += 32) {
            __syncthreads();
            float4 hv = *(const float4*)(hsrc + k0 * BB);
            ((float4*)&As[0][0])[tid] = hv;
            float4 wv = *(const float4*)(wrow + k0);
            Ws[wl * 4 + 0][wr] = wv.x; Ws[wl * 4 + 1][wr] = wv.y;
            Ws[wl * 4 + 2][wr] = wv.z; Ws[wl * 4 + 3][wr] = wv.w;
            __syncthreads();
#pragma unroll
            for (int kk = 0; kk < 32; kk++) {
                float a = As[kk][ty];
                float4 w = *(const float4*)&Ws[kk][tx * 4];
                acc0 = fmaf(a, w.x, acc0);
                acc1 = fmaf(a, w.y, acc1);
                acc2 = fmaf(a, w.z, acc2);
                acc3 = fmaf(a, w.w, acc3);
            }
        }
    }

    int b = ty, j = j0 + tx;
    const float* g = Gp + b * G4;
    float gi = acc0 + g[j];
    float gf = acc1 + g[HH + j];
    float gg = acc2 + g[2 * HH + j];
    float go = acc3 + g[3 * HH + j];
    float cp = (t > 0) ? cbuf[j * BB + b] : 0.f;
    float cn = sigmf(gf) * cp + sigmf(gi) * tanhf(gg);
    float hh = sigmf(go) * tanhf(cn);
    cbuf[j * BB + b] = cn;
    hout[j * BB + b] = hh;
    xcat[(size_t)b * K1 + j] = hh;
}

// ---------------- final projection: out[b][s][c] ---------------------------
__global__ __launch_bounds__(256) void outk(const float* __restrict__ Wout,
                                            const float* __restrict__ bout,
                                            float* __restrict__ out) {
    int bi = blockIdx.x;  // b*256+s
    int b = bi >> 8, s = bi & 255;
    const float* xr = d_x2 + (size_t)(s * BB + b) * K1;
    __shared__ float xs[K1];
    int tid = threadIdx.x;
    ((float4*)xs)[tid] = ((const float4*)xr)[tid];
    __syncthreads();
    int g = tid >> 3, lane = tid & 7;
    int gc = (g < CC) ? g : (CC - 1);
    const float* w = Wout + (size_t)gc * K1;
    float sum = 0.f;
    for (int k = lane; k < K1; k += 8) sum = fmaf(xs[k], w[k], sum);
    sum += __shfl_down_sync(0xffffffffu, sum, 4, 8);
    sum += __shfl_down_sync(0xffffffffu, sum, 2, 8);
    sum += __shfl_down_sync(0xffffffffu, sum, 1, 8);
    if (lane == 0 && g < CC)
        out[((size_t)b * SS + s) * CC + g] = sum + bout[g];
}

// ---------------- launch ----------------------------------------------------
extern "C" void kernel_launch(void* const* d_in, const int* in_sizes, int n_in,
                              void* d_out, int out_size) {
    const float* hs     = (const float*)d_in[0];
    const int*   roles  = (const int*)d_in[1];
    const int*   preds  = (const int*)d_in[2];
    const float* Wih0f  = (const float*)d_in[3];
    const float* Whh0f  = (const float*)d_in[4];
    const float* bih0f  = (const float*)d_in[5];
    const float* bhh0f  = (const float*)d_in[6];
    const float* Wih0b  = (const float*)d_in[7];
    const float* Whh0b  = (const float*)d_in[8];
    const float* bih0b  = (const float*)d_in[9];
    const float* bhh0b  = (const float*)d_in[10];
    const float* Wih1f  = (const float*)d_in[11];
    const float* Whh1f  = (const float*)d_in[12];
    const float* bih1f  = (const float*)d_in[13];
    const float* bhh1f  = (const float*)d_in[14];
    const float* Wih1b  = (const float*)d_in[15];
    const float* Whh1b  = (const float*)d_in[16];
    const float* bih1b  = (const float*)d_in[17];
    const float* bhh1b  = (const float*)d_in[18];
    const float* Wout   = (const float*)d_in[19];
    const float* bout   = (const float*)d_in[20];
    float* out = (float*)d_out;

    // feature prep
    prep_mean<<<MTOT, 256>>>(hs);
    predk<<<1, 32>>>(preds);
    finishx<<<32, 256>>>(roles);
    wpadk<<<12416, 256>>>(Wih0f, Wih0b);

    dim3 gg(G4 / 128, MTOT / 128);  // (16, 64)

    // layer 0
    sgemm_bias<<<gg, 256>>>(nullptr, bih0f, bhh0f, 0, 0);
    sgemm_bias<<<gg, 256>>>(nullptr, bih0b, bhh0b, 1, 0);
    for (int t = 0; t < SS; t++) lstm_step<<<128, 256>>>(Whh0f, Whh0b, t, 0);

    // layer 1
    sgemm_bias<<<gg, 256>>>(Wih1f, bih1f, bhh1f, 0, 1);
    sgemm_bias<<<gg, 256>>>(Wih1b, bih1b, bhh1b, 1, 1);
    for (int t = 0; t < SS; t++) lstm_step<<<128, 256>>>(Whh1f, Whh1b, t, 1);

    // output projection
    outk<<<MTOT, 256>>>(Wout, bout, out);
}